// round 1
// baseline (speedup 1.0000x reference)
#include <cuda_runtime.h>
#include <math.h>

// Shapes (fixed by the problem)
#define H    768
#define T    512
#define NC   8
#define NCT  4096        // NC*T
#define NL   8921
#define NN   4
#define RSPLIT 1115      // lw rows 1115*c (c=1..7) are split across chunks c-1/c

// Partition config
#define NSUB     8       // 512 rows per chunk -> 8 sub-blocks of 64 rows
#define SUBROWS  64
#define NSLICE   24      // lw row slices
#define SLICELEN 372     // ceil(8921/24)
#define KG       6       // 768 = 6 * 128

#define NB_B (NC * NSUB * KG)   // 384 encoding-block-sum blocks
#define NB_L (NSLICE * KG)      // 144 lw-partial blocks

__device__ float g_Bsub[NC * NSUB * H];     // [chunk][sub][k]
__device__ float g_Lpart[NSLICE * 8 * H];   // [slice][chunk][k]

// note_end_chunk_ids may be int32 or int64 on device; detect from word pattern.
// int64 little-endian values in [0,8) look like [v0,0,v1,0,v2,0,v3,0].
__device__ __forceinline__ void load_ids(const int* __restrict__ w, int ids[4]) {
    int a0 = w[0], a1 = w[1], a2 = w[2], a3 = w[3];
    bool maybe64 = (a1 == 0 && a3 == 0 && a0 >= 0 && a0 < NC && a2 >= a0 && a2 < NC);
    if (maybe64) {
        int b2 = w[4], b2h = w[5], b3 = w[6], b3h = w[7];
        if (b2h == 0 && b3h == 0 && b2 >= a2 && b2 < NC && b3 >= b2 && b3 < NC) {
            ids[0] = a0; ids[1] = a2; ids[2] = b2; ids[3] = b3;
            return;
        }
    }
    ids[0] = a0; ids[1] = a1; ids[2] = a2; ids[3] = a3;
}

// Fused main pass: block-column-sums of encoding + per-chunk row-sums of lw.
__global__ void __launch_bounds__(128, 8)
k_main(const float* __restrict__ enc, const float* __restrict__ lw) {
    int b = blockIdx.x;
    int t = threadIdx.x;
    if (b < NB_B) {
        // B[chunk][sub][k] = sum over 64 encoding rows of column k
        int kg    = b % KG;
        int cs    = b / KG;            // 0..63
        int chunk = cs / NSUB;
        int sub   = cs % NSUB;
        int k     = kg * 128 + t;
        const float* p = enc + (size_t)(chunk * T + sub * SUBROWS) * H + k;
        float s = 0.f;
        #pragma unroll 16
        for (int r = 0; r < SUBROWS; ++r) s += p[(size_t)r * H];
        g_Bsub[(chunk * NSUB + sub) * H + k] = s;
    } else {
        // Lpart[slice][chunk][k] = sum of lw[i][k] over full rows of that chunk in slice
        int b3 = b - NB_B;
        int kg = b3 % KG;
        int is = b3 / KG;              // 0..NSLICE-1
        int k  = kg * 128 + t;
        int i0 = is * SLICELEN;
        int i1 = min(i0 + SLICELEN, NL);
        float seg0 = 0.f, seg1 = 0.f;
        int   sc0 = -1,   sc1 = -1;
        int i = i0;
        while (i < i1) {
            int c   = i / RSPLIT;
            int rem = i - c * RSPLIT;
            if (rem == 0 && c >= 1 && c <= 7) { ++i; continue; }  // split row: handled in k_final
            int ch = (c > 7) ? 7 : c;                             // row 8920 -> chunk 7
            int segend = min(i1, (c + 1) * RSPLIT);
            const float* p = lw + (size_t)i * H + k;
            int n = segend - i;
            float s = 0.f;
            #pragma unroll 16
            for (int r = 0; r < n; ++r) s += p[(size_t)r * H];
            i = segend;
            if (sc0 < 0 || sc0 == ch) { sc0 = ch; seg0 += s; }
            else                      { sc1 = ch; seg1 += s; }
        }
        #pragma unroll
        for (int c = 0; c < 8; ++c) {
            float v = (c == sc0) ? seg0 : ((c == sc1) ? seg1 : 0.f);
            g_Lpart[(is * 8 + c) * H + k] = v;
        }
    }
}

// Final combine: tiny (768 lanes of k).
__global__ void __launch_bounds__(128)
k_final(const float* __restrict__ lw, const int* __restrict__ idw,
        float* __restrict__ out) {
    int k = blockIdx.x * 128 + threadIdx.x;   // grid = 6

    int ids[4];
    load_ids(idw, ids);
    float v[4][8];
    #pragma unroll
    for (int c = 0; c < 8; ++c) {
        int cnt = 0;
        #pragma unroll
        for (int n = 0; n < 4; ++n) cnt += (ids[n] < c);
        float inv = (cnt > 0) ? 1.f / (float)cnt : 0.f;
        #pragma unroll
        for (int n = 0; n < 4; ++n)
            v[n][c] = (cnt == 0) ? 0.25f : ((ids[n] < c) ? inv : 0.f);
    }

    // Per-chunk encoding column sums + prefixes
    float B[8];
    #pragma unroll
    for (int c = 0; c < 8; ++c) {
        float s = 0.f;
        #pragma unroll
        for (int sub = 0; sub < NSUB; ++sub) s += g_Bsub[(c * NSUB + sub) * H + k];
        B[c] = s;
    }
    float P[9];
    P[0] = 0.f;
    #pragma unroll
    for (int c = 0; c < 8; ++c) P[c + 1] = P[c] + B[c];
    float E = P[8];

    // Reduce lw partials
    float L[8];
    #pragma unroll
    for (int c = 0; c < 8; ++c) {
        float s = 0.f;
        #pragma unroll
        for (int is = 0; is < NSLICE; ++is) s += g_Lpart[(is * 8 + c) * H + k];
        L[c] = s;
    }

    // S_c[k] = L_c*E + split-row boundary terms
    float S[8];
    #pragma unroll
    for (int c = 0; c < 8; ++c) {
        float s = L[c] * E;
        if (c >= 1) s += lw[(size_t)(RSPLIT * c) * H + k] * (E - P[c]);
        if (c <= 6) s += lw[(size_t)(RSPLIT * (c + 1)) * H + k] * P[c + 1];
        S[c] = s;
    }

    #pragma unroll
    for (int n = 0; n < 4; ++n) {
        float sc = 0.f;
        #pragma unroll
        for (int c = 0; c < 8; ++c) sc += v[n][c] * S[c];
        out[n * H + k] = 1.f / (1.f + expf(-sc));
    }
}

extern "C" void kernel_launch(void* const* d_in, const int* in_sizes, int n_in,
                              void* d_out, int out_size) {
    // Locate inputs by element count; fall back to declared order.
    int ie = 0, ilw = 2, iid = 3;
    int hnl_seen = 0;
    for (int i = 0; i < n_in; ++i) {
        long long sz = in_sizes[i];
        if (sz == (long long)NCT * H) ie = i;
        else if (sz == (long long)H * NL) { if (hnl_seen++) ilw = i; }
        else if (sz == NN) iid = i;
    }
    const float* enc = (const float*)d_in[ie];
    const float* lw  = (const float*)d_in[ilw];
    const int*   idw = (const int*)d_in[iid];

    k_main<<<NB_B + NB_L, 128>>>(enc, lw);
    k_final<<<KG, 128>>>(lw, idw, (float*)d_out);
}

// round 3
// speedup vs baseline: 1.1867x; 1.1867x over previous
#include <cuda_runtime.h>
#include <math.h>

// Shapes (fixed by the problem)
#define H    768
#define T    512
#define NC   8
#define NCT  4096        // NC*T
#define NL   8921
#define NN   4
#define RSPLIT 1115      // lw rows 1115*c (c=1..7) are split across chunks c-1/c

// Partition config
#define NSUB     8       // 512 rows per chunk -> 8 sub-blocks of 64 rows
#define NSLICE   96      // lw row slices
#define SLICELEN 93      // ceil(8921/96)
#define H4       192     // H / 4

#define NB_ENC (NC * NSUB)        // 64 encoding blocks
#define NB_LW  NSLICE             // 96 lw blocks

__device__ float g_Bsub[NB_ENC * H];        // [chunk*8+sub][k]
__device__ float g_Lpart[NSLICE * 8 * H];   // [slice][chunk][k]
__device__ float g_B[8 * H];                // reduced per-chunk enc col sums
__device__ float g_L[8 * H];                // reduced per-chunk lw row sums

// note_end_chunk_ids may be int32 or int64 on device; detect from word pattern.
__device__ __forceinline__ void load_ids(const int* __restrict__ w, int ids[4]) {
    int a0 = w[0], a1 = w[1], a2 = w[2], a3 = w[3];
    bool maybe64 = (a1 == 0 && a3 == 0 && a0 >= 0 && a0 < NC && a2 >= a0 && a2 < NC);
    if (maybe64) {
        int b2 = w[4], b2h = w[5], b3 = w[6], b3h = w[7];
        if (b2h == 0 && b3h == 0 && b2 >= a2 && b2 < NC && b3 >= b2 && b3 < NC) {
            ids[0] = a0; ids[1] = a2; ids[2] = b2; ids[3] = b3;
            return;
        }
    }
    ids[0] = a0; ids[1] = a1; ids[2] = a2; ids[3] = a3;
}

__device__ __forceinline__ void acc4(float4& s, const float4 v) {
    s.x += v.x; s.y += v.y; s.z += v.z; s.w += v.w;
}

// Streaming pass: float4, one full 768-col row per 192-thread block.
__global__ void __launch_bounds__(192, 8)
k_main(const float* __restrict__ enc, const float* __restrict__ lw) {
    int b = blockIdx.x;
    int t = threadIdx.x;           // k4 lane, 0..191
    if (b < NB_ENC) {
        int chunk = b >> 3, sub = b & 7;
        const float4* p = (const float4*)enc + (size_t)(chunk * T + sub * 64) * H4 + t;
        float4 s0 = {0,0,0,0}, s1 = {0,0,0,0};
        #pragma unroll 8
        for (int r = 0; r < 64; r += 2) {
            acc4(s0, p[(size_t)r * H4]);
            acc4(s1, p[(size_t)(r + 1) * H4]);
        }
        acc4(s0, s1);
        ((float4*)g_Bsub)[(chunk * 8 + sub) * H4 + t] = s0;
    } else {
        int is = b - NB_ENC;
        int i0 = is * SLICELEN;
        int i1 = min(i0 + SLICELEN, NL);
        float4 seg0 = {0,0,0,0}, seg1 = {0,0,0,0};
        int   sc0 = -1, sc1 = -1;
        int i = i0;
        while (i < i1) {
            int c   = i / RSPLIT;
            int rem = i - c * RSPLIT;
            if (rem == 0 && c >= 1 && c <= 7) { ++i; continue; }  // split row: handled in k_final
            int ch = (c > 7) ? 7 : c;                             // row 8920 -> chunk 7
            int segend = min(i1, (c + 1) * RSPLIT);
            const float4* p = (const float4*)lw + (size_t)i * H4 + t;
            float4 s = {0,0,0,0};
            int n = segend - i;
            #pragma unroll 8
            for (int r = 0; r < n; ++r) acc4(s, p[(size_t)r * H4]);
            i = segend;
            if (sc0 < 0 || sc0 == ch) { sc0 = ch; acc4(seg0, s); }
            else                      { sc1 = ch; acc4(seg1, s); }
        }
        #pragma unroll
        for (int c = 0; c < 8; ++c) {
            float4 v = {0,0,0,0};
            if (c == sc0) v = seg0;
            else if (c == sc1) v = seg1;
            ((float4*)g_Lpart)[(is * 8 + c) * H4 + t] = v;
        }
    }
}

// Parallel tree reduce of partials: grid = 8 chunks x 6 k-groups.
__global__ void __launch_bounds__(128)
k_reduce() {
    int c  = blockIdx.x / 6;
    int kg = blockIdx.x % 6;
    int k  = kg * 128 + threadIdx.x;

    float sb = 0.f;
    #pragma unroll
    for (int sub = 0; sub < 8; ++sub) sb += g_Bsub[(c * 8 + sub) * H + k];
    g_B[c * H + k] = sb;

    float a0 = 0.f, a1 = 0.f, a2 = 0.f, a3 = 0.f;
    #pragma unroll
    for (int is = 0; is < NSLICE; is += 4) {
        a0 += g_Lpart[((is + 0) * 8 + c) * H + k];
        a1 += g_Lpart[((is + 1) * 8 + c) * H + k];
        a2 += g_Lpart[((is + 2) * 8 + c) * H + k];
        a3 += g_Lpart[((is + 3) * 8 + c) * H + k];
    }
    g_L[c * H + k] = (a0 + a1) + (a2 + a3);
}

// Final combine: tiny (768 lanes of k), ~30 loads per thread.
__global__ void __launch_bounds__(128)
k_final(const float* __restrict__ lw, const int* __restrict__ idw,
        float* __restrict__ out) {
    int k = blockIdx.x * 128 + threadIdx.x;   // grid = 6

    int ids[4];
    load_ids(idw, ids);
    float v[4][8];
    #pragma unroll
    for (int c = 0; c < 8; ++c) {
        int cnt = 0;
        #pragma unroll
        for (int n = 0; n < 4; ++n) cnt += (ids[n] < c);
        float inv = (cnt > 0) ? 1.f / (float)cnt : 0.f;
        #pragma unroll
        for (int n = 0; n < 4; ++n)
            v[n][c] = (cnt == 0) ? 0.25f : ((ids[n] < c) ? inv : 0.f);
    }

    float B[8], L[8];
    #pragma unroll
    for (int c = 0; c < 8; ++c) { B[c] = g_B[c * H + k]; L[c] = g_L[c * H + k]; }

    float P[9];
    P[0] = 0.f;
    #pragma unroll
    for (int c = 0; c < 8; ++c) P[c + 1] = P[c] + B[c];
    float E = P[8];

    // S_c[k] = L_c*E + split-row boundary terms
    float S[8];
    #pragma unroll
    for (int c = 0; c < 8; ++c) {
        float s = L[c] * E;
        if (c >= 1) s += lw[(size_t)(RSPLIT * c) * H + k] * (E - P[c]);
        if (c <= 6) s += lw[(size_t)(RSPLIT * (c + 1)) * H + k] * P[c + 1];
        S[c] = s;
    }

    #pragma unroll
    for (int n = 0; n < 4; ++n) {
        float sc = 0.f;
        #pragma unroll
        for (int c = 0; c < 8; ++c) sc += v[n][c] * S[c];
        out[n * H + k] = 1.f / (1.f + expf(-sc));
    }
}

extern "C" void kernel_launch(void* const* d_in, const int* in_sizes, int n_in,
                              void* d_out, int out_size) {
    // Locate inputs by element count; fall back to declared order.
    int ie = 0, ilw = 2, iid = 3;
    int hnl_seen = 0;
    for (int i = 0; i < n_in; ++i) {
        long long sz = in_sizes[i];
        if (sz == (long long)NCT * H) ie = i;
        else if (sz == (long long)H * NL) { if (hnl_seen++) ilw = i; }
        else if (sz == NN) iid = i;
    }
    const float* enc = (const float*)d_in[ie];
    const float* lw  = (const float*)d_in[ilw];
    const int*   idw = (const int*)d_in[iid];

    k_main<<<NB_ENC + NB_LW, 192>>>(enc, lw);
    k_reduce<<<48, 128>>>();
    k_final<<<6, 128>>>(lw, idw, (float*)d_out);
}

// round 4
// speedup vs baseline: 1.8265x; 1.5392x over previous
#include <cuda_runtime.h>
#include <math.h>

// Shapes (fixed by the problem)
#define H    768
#define T    512
#define NC   8
#define NCT  4096
#define NL   8921
#define NN   4
#define RSPLIT 1115      // lw rows 1115*c (c=1..7) are split across chunks c-1/c

// Partition config
#define NSUB     32      // 512 rows per chunk -> 32 sub-blocks of 16 rows
#define SUBROWS  16
#define SLICELEN 24
#define NSLICE   372     // ceil(8921/24)
#define H4       192     // H / 4

#define NB_ENC (NC * NSUB)        // 256 encoding blocks
#define NB_LW  NSLICE             // 372 lw blocks

__device__ float g_B[8 * H];     // per-chunk enc column sums (atomic accum)
__device__ float g_L[8 * H];     // per-chunk lw row sums     (atomic accum)

// note_end_chunk_ids may be int32 or int64 on device; detect from word pattern.
__device__ __forceinline__ void load_ids(const int* __restrict__ w, int ids[4]) {
    int a0 = w[0], a1 = w[1], a2 = w[2], a3 = w[3];
    bool maybe64 = (a1 == 0 && a3 == 0 && a0 >= 0 && a0 < NC && a2 >= a0 && a2 < NC);
    if (maybe64) {
        int b2 = w[4], b2h = w[5], b3 = w[6], b3h = w[7];
        if (b2h == 0 && b3h == 0 && b2 >= a2 && b2 < NC && b3 >= b2 && b3 < NC) {
            ids[0] = a0; ids[1] = a2; ids[2] = b2; ids[3] = b3;
            return;
        }
    }
    ids[0] = a0; ids[1] = a1; ids[2] = a2; ids[3] = a3;
}

__device__ __forceinline__ void acc4(float4& s, const float4 v) {
    s.x += v.x; s.y += v.y; s.z += v.z; s.w += v.w;
}

__device__ __forceinline__ void red4(float* dst, int k4, const float4 v) {
    atomicAdd(dst + k4 * 4 + 0, v.x);
    atomicAdd(dst + k4 * 4 + 1, v.y);
    atomicAdd(dst + k4 * 4 + 2, v.z);
    atomicAdd(dst + k4 * 4 + 3, v.w);
}

// Streaming pass: float4, one full 768-col row per 192-thread block.
// Fine-grained (16/24-row) work units; REDG accumulate into g_B / g_L.
__global__ void __launch_bounds__(192, 8)
k_main(const float* __restrict__ enc, const float* __restrict__ lw) {
    int b = blockIdx.x;
    int t = threadIdx.x;           // k4 lane, 0..191
    if (b < NB_ENC) {
        int chunk = b >> 5, sub = b & 31;
        const float4* p = (const float4*)enc + (size_t)(chunk * T + sub * SUBROWS) * H4 + t;
        float4 a[8];
        #pragma unroll
        for (int i = 0; i < 8; ++i) a[i] = make_float4(0.f, 0.f, 0.f, 0.f);
        #pragma unroll
        for (int r = 0; r < SUBROWS; ++r) acc4(a[r & 7], p[(size_t)r * H4]);
        #pragma unroll
        for (int i = 0; i < 4; ++i) acc4(a[i], a[i + 4]);
        acc4(a[0], a[2]); acc4(a[1], a[3]); acc4(a[0], a[1]);
        red4(g_B + chunk * H, t, a[0]);
    } else {
        int is = b - NB_ENC;
        int i0 = is * SLICELEN;
        int i1 = min(i0 + SLICELEN, NL);
        int i = i0;
        while (i < i1) {
            int c   = i / RSPLIT;
            int rem = i - c * RSPLIT;
            if (rem == 0 && c >= 1 && c <= 7) { ++i; continue; }  // split row: handled in k_final
            int ch = (c > 7) ? 7 : c;                             // row 8920 -> chunk 7
            int segend = min(i1, (c + 1) * RSPLIT);
            const float4* p = (const float4*)lw + (size_t)i * H4 + t;
            int n = segend - i;
            float4 a[4];
            #pragma unroll
            for (int j = 0; j < 4; ++j) a[j] = make_float4(0.f, 0.f, 0.f, 0.f);
            #pragma unroll 8
            for (int r = 0; r < n; ++r) acc4(a[r & 3], p[(size_t)r * H4]);
            acc4(a[0], a[2]); acc4(a[1], a[3]); acc4(a[0], a[1]);
            red4(g_L + ch * H, t, a[0]);
            i = segend;
        }
    }
}

// Final combine: tiny (768 lanes of k), ~30 loads per thread.
__global__ void __launch_bounds__(128)
k_final(const float* __restrict__ lw, const int* __restrict__ idw,
        float* __restrict__ out) {
    int k = blockIdx.x * 128 + threadIdx.x;   // grid = 6

    int ids[4];
    load_ids(idw, ids);
    float v[4][8];
    #pragma unroll
    for (int c = 0; c < 8; ++c) {
        int cnt = 0;
        #pragma unroll
        for (int n = 0; n < 4; ++n) cnt += (ids[n] < c);
        float inv = (cnt > 0) ? 1.f / (float)cnt : 0.f;
        #pragma unroll
        for (int n = 0; n < 4; ++n)
            v[n][c] = (cnt == 0) ? 0.25f : ((ids[n] < c) ? inv : 0.f);
    }

    float B[8], L[8];
    #pragma unroll
    for (int c = 0; c < 8; ++c) { B[c] = g_B[c * H + k]; L[c] = g_L[c * H + k]; }

    float P[9];
    P[0] = 0.f;
    #pragma unroll
    for (int c = 0; c < 8; ++c) P[c + 1] = P[c] + B[c];
    float E = P[8];

    // S_c[k] = L_c*E + split-row boundary terms
    float S[8];
    #pragma unroll
    for (int c = 0; c < 8; ++c) {
        float s = L[c] * E;
        if (c >= 1) s += lw[(size_t)(RSPLIT * c) * H + k] * (E - P[c]);
        if (c <= 6) s += lw[(size_t)(RSPLIT * (c + 1)) * H + k] * P[c + 1];
        S[c] = s;
    }

    #pragma unroll
    for (int n = 0; n < 4; ++n) {
        float sc = 0.f;
        #pragma unroll
        for (int c = 0; c < 8; ++c) sc += v[n][c] * S[c];
        out[n * H + k] = 1.f / (1.f + expf(-sc));
    }
}

extern "C" void kernel_launch(void* const* d_in, const int* in_sizes, int n_in,
                              void* d_out, int out_size) {
    // Locate inputs by element count; fall back to declared order.
    int ie = 0, ilw = 2, iid = 3;
    int hnl_seen = 0;
    for (int i = 0; i < n_in; ++i) {
        long long sz = in_sizes[i];
        if (sz == (long long)NCT * H) ie = i;
        else if (sz == (long long)H * NL) { if (hnl_seen++) ilw = i; }
        else if (sz == NN) iid = i;
    }
    const float* enc = (const float*)d_in[ie];
    const float* lw  = (const float*)d_in[ilw];
    const int*   idw = (const int*)d_in[iid];

    void* pB = nullptr; void* pL = nullptr;
    cudaGetSymbolAddress(&pB, g_B);
    cudaGetSymbolAddress(&pL, g_L);
    cudaMemsetAsync(pB, 0, 8 * H * sizeof(float));
    cudaMemsetAsync(pL, 0, 8 * H * sizeof(float));

    k_main<<<NB_ENC + NB_LW, 192>>>(enc, lw);
    k_final<<<6, 128>>>(lw, idw, (float*)d_out);
}